// round 1
// baseline (speedup 1.0000x reference)
#include <cuda_runtime.h>

#define WINDOW   512
#define PREFIX   16
#define SEQ      4096
#define NH       16
#define BATCH    2
#define DM       1024
#define HD       64

// Scratch (device globals; allocation APIs are forbidden).
__device__ float g_q[(size_t)BATCH * NH * SEQ * HD];   // [b*16+h][s][d]
__device__ float g_k[(size_t)BATCH * NH * SEQ * HD];
__device__ float g_v[(size_t)BATCH * NH * SEQ * HD];
__device__ float g_o[(size_t)BATCH * SEQ * DM];        // [b][s][h*64+d]

// ---------------------------------------------------------------------------
// SGEMM (NT): C[m,n] = sum_k A[m,k] * B[n,k]. M=8192, K=1024.
// QKV=true : A = x, scatter output into g_q/g_k/g_v ([bh][s][d] layout).
// QKV=false: A = g_o, store plain to Cout (N = 1024).
// ---------------------------------------------------------------------------
template<bool QKV>
__global__ __launch_bounds__(256)
void sgemm_nt(const float* __restrict__ Ain,
              const float* __restrict__ Bw,
              float* __restrict__ Cout)
{
    __shared__ float As[16][132];   // [k][m], padded: conflict-free ld & st
    __shared__ float Bs[16][132];   // [k][n]

    const float* A = QKV ? Ain : g_o;

    const int tid = threadIdx.x;
    const int ty  = tid >> 4;       // 0..15
    const int tx  = tid & 15;       // 0..15
    const int m0  = blockIdx.y << 7;
    const int n0  = blockIdx.x << 7;

    float acc[8][8];
    #pragma unroll
    for (int i = 0; i < 8; ++i)
        #pragma unroll
        for (int j = 0; j < 8; ++j) acc[i][j] = 0.0f;

    for (int k0 = 0; k0 < 1024; k0 += 16) {
        #pragma unroll
        for (int t = 0; t < 2; ++t) {
            int idx = tid + (t << 8);        // 0..511 float4 slots
            int row = idx >> 2;              // 0..127
            int c4  = (idx & 3) << 2;        // 0,4,8,12
            float4 va = *(const float4*)(A  + (size_t)(m0 + row) * 1024 + k0 + c4);
            float4 vb = *(const float4*)(Bw + (size_t)(n0 + row) * 1024 + k0 + c4);
            As[c4 + 0][row] = va.x; As[c4 + 1][row] = va.y;
            As[c4 + 2][row] = va.z; As[c4 + 3][row] = va.w;
            Bs[c4 + 0][row] = vb.x; Bs[c4 + 1][row] = vb.y;
            Bs[c4 + 2][row] = vb.z; Bs[c4 + 3][row] = vb.w;
        }
        __syncthreads();

        #pragma unroll
        for (int kk = 0; kk < 16; ++kk) {
            float a[8], b[8];
            *(float4*)&a[0] = *(const float4*)&As[kk][ty * 8];
            *(float4*)&a[4] = *(const float4*)&As[kk][ty * 8 + 4];
            *(float4*)&b[0] = *(const float4*)&Bs[kk][tx * 8];
            *(float4*)&b[4] = *(const float4*)&Bs[kk][tx * 8 + 4];
            #pragma unroll
            for (int i = 0; i < 8; ++i)
                #pragma unroll
                for (int j = 0; j < 8; ++j)
                    acc[i][j] = fmaf(a[i], b[j], acc[i][j]);
        }
        __syncthreads();
    }

    #pragma unroll
    for (int i = 0; i < 8; ++i) {
        int m = m0 + ty * 8 + i;
        int n = n0 + tx * 8;
        float4 v0 = make_float4(acc[i][0], acc[i][1], acc[i][2], acc[i][3]);
        float4 v1 = make_float4(acc[i][4], acc[i][5], acc[i][6], acc[i][7]);
        if (QKV) {
            int bb   = m >> 12;          // m / 4096
            int s    = m & 4095;
            int part = n >> 10;          // 0:q 1:k 2:v (tile never straddles)
            int nn   = n & 1023;
            int h    = nn >> 6;
            int d    = nn & 63;          // 8 cols stay inside one head
            float* dst = (part == 0) ? g_q : ((part == 1) ? g_k : g_v);
            size_t off = (((size_t)(bb * NH + h)) * SEQ + s) * HD + d;
            *(float4*)(dst + off)     = v0;
            *(float4*)(dst + off + 4) = v1;
        } else {
            size_t off = (size_t)m * DM + n;
            *(float4*)(Cout + off)     = v0;
            *(float4*)(Cout + off + 4) = v1;
        }
    }
}

// ---------------------------------------------------------------------------
// Attention: one block = 32 queries of one (b,h). Flash-style online softmax
// over 64-key tiles: prefix tile 0 (if not already in window) + window tiles.
// allowed(q,k) = (k <= q) && (k < 16 || q-k < 512)
// threads: 256 = 8 warps; warp ty owns query rows ty*4..ty*4+3;
// lane owns keys {lane, lane+32} and output dims {lane, lane+32}.
// ---------------------------------------------------------------------------
__global__ __launch_bounds__(256)
void attn_kernel()
{
    __shared__ float Qs[32][64];       // [q][d]  (reads are warp-broadcast)
    __shared__ float Kst[64][65];      // [d][key] transposed; P overlaid later
    __shared__ float Vs[64][64];       // [key][d]
    float* Ps = &Kst[0][0];            // P[r][k] at Ps[r*64+k]; 2048 <= 4160

    const int tid  = threadIdx.x;
    const int lane = tid & 31;
    const int ty   = tid >> 5;                    // 0..7
    const int bh   = blockIdx.y;                  // 0..31
    const int t0   = blockIdx.x * 32;

    const float* Qg = g_q + (size_t)bh * SEQ * HD + (size_t)t0 * HD;
    const float* Kg = g_k + (size_t)bh * SEQ * HD;
    const float* Vg = g_v + (size_t)bh * SEQ * HD;

    // Load Q tile (2048 floats = 512 float4)
    #pragma unroll
    for (int t = 0; t < 2; ++t) {
        int idx = tid + (t << 8);
        int row = idx >> 4;
        int c4  = (idx & 15) << 2;
        *(float4*)&Qs[row][c4] = *(const float4*)(Qg + (size_t)row * HD + c4);
    }

    float m_i[4], l_i[4], o0[4], o1[4];
    #pragma unroll
    for (int i = 0; i < 4; ++i) { m_i[i] = -1e30f; l_i[i] = 0.0f; o0[i] = 0.0f; o1[i] = 0.0f; }

    int lo = t0 - (WINDOW - 1); if (lo < 0) lo = 0;
    const int lo_tile = lo >> 6;
    const int hi_tile = (t0 + 31) >> 6;
    const int extra   = (lo_tile > 0) ? 1 : 0;    // separate prefix tile 0
    const int ntiles  = hi_tile - lo_tile + 1 + extra;

    for (int it = 0; it < ntiles; ++it) {
        int kt = extra ? ((it == 0) ? 0 : (lo_tile + it - 1)) : (lo_tile + it);
        int kbase = kt << 6;

        __syncthreads();   // previous PV done with Vs / Ps
        // Load K (transposed) and V: 1024 float4 each side -> 4 per thread
        #pragma unroll
        for (int t = 0; t < 4; ++t) {
            int idx = tid + (t << 8);
            int row = idx >> 4;                  // key 0..63
            int c4  = (idx & 15) << 2;           // d
            float4 kv = *(const float4*)(Kg + (size_t)(kbase + row) * HD + c4);
            Kst[c4 + 0][row] = kv.x; Kst[c4 + 1][row] = kv.y;
            Kst[c4 + 2][row] = kv.z; Kst[c4 + 3][row] = kv.w;
            *(float4*)&Vs[row][c4] = *(const float4*)(Vg + (size_t)(kbase + row) * HD + c4);
        }
        __syncthreads();

        // Scores: s[i][jj] = Q[ty*4+i][:] . K[jj*32+lane][:]
        float s[4][2];
        #pragma unroll
        for (int i = 0; i < 4; ++i) { s[i][0] = 0.0f; s[i][1] = 0.0f; }
        #pragma unroll 4
        for (int d = 0; d < 64; ++d) {
            float k0v = Kst[d][lane];
            float k1v = Kst[d][lane + 32];
            #pragma unroll
            for (int i = 0; i < 4; ++i) {
                float qv = Qs[ty * 4 + i][d];
                s[i][0] = fmaf(qv, k0v, s[i][0]);
                s[i][1] = fmaf(qv, k1v, s[i][1]);
            }
        }

        // Mask + scale, online softmax update
        float pr[4][2];
        #pragma unroll
        for (int i = 0; i < 4; ++i) {
            int q = t0 + ty * 4 + i;
            #pragma unroll
            for (int jj = 0; jj < 2; ++jj) {
                int k = kbase + lane + jj * 32;
                bool ok = (k <= q) && ((k < PREFIX) || ((q - k) < WINDOW));
                s[i][jj] = ok ? s[i][jj] * 0.125f : -1e30f;
            }
            float mx = fmaxf(s[i][0], s[i][1]);
            #pragma unroll
            for (int off = 16; off > 0; off >>= 1)
                mx = fmaxf(mx, __shfl_xor_sync(0xffffffffu, mx, off));
            float mnew  = fmaxf(m_i[i], mx);
            float scale = __expf(m_i[i] - mnew);
            float p0 = __expf(s[i][0] - mnew);
            float p1 = __expf(s[i][1] - mnew);
            float rs = p0 + p1;
            #pragma unroll
            for (int off = 16; off > 0; off >>= 1)
                rs += __shfl_xor_sync(0xffffffffu, rs, off);
            l_i[i] = l_i[i] * scale + rs;
            m_i[i] = mnew;
            o0[i] *= scale; o1[i] *= scale;
            pr[i][0] = p0; pr[i][1] = p1;
        }

        __syncthreads();   // everyone done reading Kst before P overwrite
        #pragma unroll
        for (int i = 0; i < 4; ++i) {
            Ps[(ty * 4 + i) * 64 + lane]      = pr[i][0];
            Ps[(ty * 4 + i) * 64 + lane + 32] = pr[i][1];
        }
        __syncthreads();

        // O += P * V  (V reads contiguous per row; P reads broadcast)
        #pragma unroll 2
        for (int k = 0; k < 64; ++k) {
            float v0 = Vs[k][lane];
            float v1 = Vs[k][lane + 32];
            #pragma unroll
            for (int i = 0; i < 4; ++i) {
                float p = Ps[(ty * 4 + i) * 64 + k];
                o0[i] = fmaf(p, v0, o0[i]);
                o1[i] = fmaf(p, v1, o1[i]);
            }
        }
    }

    // Finalize: g_o[b][s][h*64+d]
    const int b = bh >> 4, h = bh & 15;
    #pragma unroll
    for (int i = 0; i < 4; ++i) {
        int q = t0 + ty * 4 + i;
        float inv = 1.0f / l_i[i];
        float* dst = g_o + ((size_t)b * SEQ + q) * DM + h * HD;
        dst[lane]      = o0[i] * inv;
        dst[lane + 32] = o1[i] * inv;
    }
}

// ---------------------------------------------------------------------------
extern "C" void kernel_launch(void* const* d_in, const int* in_sizes, int n_in,
                              void* d_out, int out_size)
{
    const float* x     = (const float*)d_in[0];
    const float* w_qkv = (const float*)d_in[1];
    const float* w_out = (const float*)d_in[2];
    float* out = (float*)d_out;

    // 1) QKV projection with scatter into [bh][s][d]
    sgemm_nt<true><<<dim3(3072 / 128, 8192 / 128), 256>>>(x, w_qkv, nullptr);
    // 2) windowed + prefix attention -> g_o [b][s][h*64+d]
    attn_kernel<<<dim3(SEQ / 32, BATCH * NH), 256>>>();
    // 3) output projection -> d_out
    sgemm_nt<false><<<dim3(1024 / 128, 8192 / 128), 256>>>(nullptr, w_out, out);
}

// round 3
// speedup vs baseline: 2.0047x; 2.0047x over previous
#include <cuda_runtime.h>
#include <cstdint>

#define WINDOW   512
#define PREFIX   16
#define SEQ      4096
#define NH       16
#define BATCH    2
#define DM       1024
#define HD       64

// Scratch (device globals; allocation APIs are forbidden).
__device__ float g_q[(size_t)BATCH * NH * SEQ * HD];   // [b*16+h][s][d]
__device__ float g_k[(size_t)BATCH * NH * SEQ * HD];
__device__ float g_v[(size_t)BATCH * NH * SEQ * HD];
__device__ float g_o[(size_t)BATCH * SEQ * DM];        // [b][s][h*64+d]

// ---------------------------------------------------------------------------
// cp.async helpers
// ---------------------------------------------------------------------------
__device__ __forceinline__ void cp_async16(unsigned smem_dst, const void* gsrc) {
    asm volatile("cp.async.cg.shared.global [%0], [%1], 16;\n" :: "r"(smem_dst), "l"(gsrc));
}
__device__ __forceinline__ void cp_commit() { asm volatile("cp.async.commit_group;\n"); }
__device__ __forceinline__ void cp_wait0()  { asm volatile("cp.async.wait_group 0;\n"); }

__device__ __forceinline__ unsigned f2tf32(float f) {
    unsigned r;
    asm("cvt.rna.tf32.f32 %0, %1;" : "=r"(r) : "f"(f));
    return r;
}

__device__ __forceinline__ void mma_tf32(float* c, const unsigned* a, const unsigned* b) {
    asm volatile(
        "mma.sync.aligned.m16n8k8.row.col.f32.tf32.tf32.f32 "
        "{%0,%1,%2,%3}, {%4,%5,%6,%7}, {%8,%9}, {%0,%1,%2,%3};\n"
        : "+f"(c[0]), "+f"(c[1]), "+f"(c[2]), "+f"(c[3])
        : "r"(a[0]), "r"(a[1]), "r"(a[2]), "r"(a[3]), "r"(b[0]), "r"(b[1]));
}

// ---------------------------------------------------------------------------
// TF32 tensor-core GEMM (NT): C[m,n] = sum_k A[m,k]*B[n,k].  M=8192, K=1024.
// Block tile 128x128, 256 threads (8 warps as 2x4), warp tile 64x32.
// QKV=true : A = x, scatter into g_q/g_k/g_v ([bh][s][d]); N=3072.
// QKV=false: A = g_o, plain store to Cout; N=1024.
// ---------------------------------------------------------------------------
#define KP 20   // padded k-stride (conflict-free fragment loads)

template<bool QKV>
__global__ __launch_bounds__(256)
void gemm_tc(const float* __restrict__ Ain,
             const float* __restrict__ Bw,
             float* __restrict__ Cout)
{
    __shared__ float As[2][128 * KP];
    __shared__ float Bs[2][128 * KP];

    const float* A = QKV ? Ain : g_o;

    const int tid  = threadIdx.x;
    const int lane = tid & 31;
    const int wid  = tid >> 5;
    const int wm   = wid >> 2;          // 0..1 : 64 rows
    const int wn   = wid & 3;           // 0..3 : 32 cols
    const int m0   = blockIdx.y << 7;
    const int n0   = blockIdx.x << 7;
    const int g    = lane >> 2;         // 0..7
    const int t    = lane & 3;          // 0..3

    float acc[4][4][4];
    #pragma unroll
    for (int i = 0; i < 4; ++i)
        #pragma unroll
        for (int j = 0; j < 4; ++j)
            #pragma unroll
            for (int r = 0; r < 4; ++r) acc[i][j][r] = 0.0f;

    // global->smem staging: 512 float4 per matrix, 2 per thread
    const int lrow = tid >> 2;           // 0..63
    const int lcol = (tid & 3) << 2;     // 0,4,8,12
    const float* Ag = A  + (size_t)(m0 + lrow) * 1024 + lcol;
    const float* Bg = Bw + (size_t)(n0 + lrow) * 1024 + lcol;

    const unsigned sA0 = (unsigned)__cvta_generic_to_shared(&As[0][lrow * KP + lcol]);
    const unsigned sB0 = (unsigned)__cvta_generic_to_shared(&Bs[0][lrow * KP + lcol]);
    const unsigned bufstride = 128 * KP * 4;
    const unsigned rowstride = 64 * KP * 4;

    // prologue: stage k-chunk 0 into buf 0
    cp_async16(sA0,             Ag);
    cp_async16(sA0 + rowstride, Ag + 64 * 1024);
    cp_async16(sB0,             Bg);
    cp_async16(sB0 + rowstride, Bg + 64 * 1024);
    cp_commit();
    cp_wait0();
    __syncthreads();

    int buf = 0;
    for (int kt = 0; kt < 64; ++kt) {
        if (kt + 1 < 64) {
            int k0 = (kt + 1) << 4;
            unsigned sA = sA0 + (unsigned)(buf ^ 1) * bufstride;
            unsigned sB = sB0 + (unsigned)(buf ^ 1) * bufstride;
            cp_async16(sA,             Ag + k0);
            cp_async16(sA + rowstride, Ag + 64 * 1024 + k0);
            cp_async16(sB,             Bg + k0);
            cp_async16(sB + rowstride, Bg + 64 * 1024 + k0);
            cp_commit();
        }

        const float* as = &As[buf][0];
        const float* bs = &Bs[buf][0];
        #pragma unroll
        for (int kk = 0; kk < 16; kk += 8) {
            unsigned af[4][4], bf[4][2];
            #pragma unroll
            for (int im = 0; im < 4; ++im) {
                const float* p = as + (wm * 64 + im * 16 + g) * KP + kk + t;
                af[im][0] = f2tf32(p[0]);
                af[im][1] = f2tf32(p[8 * KP]);
                af[im][2] = f2tf32(p[4]);
                af[im][3] = f2tf32(p[8 * KP + 4]);
            }
            #pragma unroll
            for (int jn = 0; jn < 4; ++jn) {
                const float* p = bs + (wn * 32 + jn * 8 + g) * KP + kk + t;
                bf[jn][0] = f2tf32(p[0]);
                bf[jn][1] = f2tf32(p[4]);
            }
            #pragma unroll
            for (int im = 0; im < 4; ++im)
                #pragma unroll
                for (int jn = 0; jn < 4; ++jn)
                    mma_tf32(acc[im][jn], af[im], bf[jn]);
        }

        cp_wait0();
        __syncthreads();
        buf ^= 1;
    }

    // epilogue: c0,c1 at (row, col..col+1); c2,c3 at (row+8, ...)
    #pragma unroll
    for (int im = 0; im < 4; ++im) {
        #pragma unroll
        for (int jn = 0; jn < 4; ++jn) {
            int row = m0 + wm * 64 + im * 16 + g;
            int col = n0 + wn * 32 + jn * 8 + (t << 1);
            float2 v0 = make_float2(acc[im][jn][0], acc[im][jn][1]);
            float2 v1 = make_float2(acc[im][jn][2], acc[im][jn][3]);
            if (QKV) {
                int part = col >> 10;            // 0:q 1:k 2:v
                int nn   = col & 1023;
                int h    = nn >> 6;
                int d    = nn & 63;              // even, pair stays in head
                float* dst = (part == 0) ? g_q : ((part == 1) ? g_k : g_v);
                int bb = row >> 12, s = row & 4095;
                size_t base = (((size_t)(bb * NH + h)) * SEQ) * HD + d;
                *(float2*)(dst + base + (size_t)s * HD)       = v0;
                *(float2*)(dst + base + (size_t)(s + 8) * HD) = v1;
            } else {
                *(float2*)(Cout + (size_t)row * DM + col)       = v0;
                *(float2*)(Cout + (size_t)(row + 8) * DM + col) = v1;
            }
        }
    }
}

// ---------------------------------------------------------------------------
// Attention: one block = 64 queries of one (b,h). Flash-style online softmax
// over 64-key tiles: optional prefix tile 0 + window tiles.
// allowed(q,k) = (k <= q) && (k < 16 || q-k < 512)
// 256 threads = 8 warps; warp ty owns rows ty*8..ty*8+7;
// lane owns keys {lane, lane+32} and output dims {lane, lane+32}.
// K stored transposed with XOR swizzle: Kst[d][key ^ KSW(d)], KSW(d)=2*(d>>2);
// conflict-free for both the transposed store and the per-d read.
// ---------------------------------------------------------------------------
#define KSW(d) ((((d) & 0x3c)) >> 1)

__global__ __launch_bounds__(256)
void attn_kernel()
{
    __shared__ float Qs[64][64];       // [q][d]   (reads are warp-broadcast)
    __shared__ float Kst[64][64];      // [d][key^swz]; P overlaid later
    __shared__ float Vs[64][64];       // [key][d]
    float* Ps = &Kst[0][0];            // P[r][k] at Ps[r*64+k] (4096 floats)

    const int tid  = threadIdx.x;
    const int lane = tid & 31;
    const int ty   = tid >> 5;                    // 0..7
    const int bh   = blockIdx.y;                  // 0..31
    const int t0   = blockIdx.x * 64;

    const float* Qg = g_q + (size_t)bh * SEQ * HD + (size_t)t0 * HD;
    const float* Kg = g_k + (size_t)bh * SEQ * HD;
    const float* Vg = g_v + (size_t)bh * SEQ * HD;

    // Load Q tile pre-scaled by 1/sqrt(64): 4096 floats = 1024 float4
    #pragma unroll
    for (int t = 0; t < 4; ++t) {
        int idx = tid + (t << 8);
        int row = idx >> 4;
        int c4  = (idx & 15) << 2;
        float4 q4 = *(const float4*)(Qg + (size_t)row * HD + c4);
        q4.x *= 0.125f; q4.y *= 0.125f; q4.z *= 0.125f; q4.w *= 0.125f;
        *(float4*)&Qs[row][c4] = q4;
    }

    float m_i[8], l_i[8], o0[8], o1[8];
    #pragma unroll
    for (int i = 0; i < 8; ++i) { m_i[i] = -1e30f; l_i[i] = 0.0f; o0[i] = 0.0f; o1[i] = 0.0f; }

    int lo = t0 - (WINDOW - 1); if (lo < 0) lo = 0;
    const int lo_tile = lo >> 6;
    const int hi_tile = (t0 + 63) >> 6;
    const int extra   = (lo_tile > 0) ? 1 : 0;    // separate prefix tile 0
    const int ntiles  = hi_tile - lo_tile + 1 + extra;

    for (int it = 0; it < ntiles; ++it) {
        int kt = extra ? ((it == 0) ? 0 : (lo_tile + it - 1)) : (lo_tile + it);
        int kbase = kt << 6;

        __syncthreads();   // previous PV done with Vs / Ps
        // Load K (transposed+swizzled) and V: 1024 float4 each -> 4/thread
        #pragma unroll
        for (int t = 0; t < 4; ++t) {
            int idx = tid + (t << 8);
            int row = idx >> 4;                  // key 0..63
            int c4  = (idx & 15) << 2;           // d
            float4 kv = *(const float4*)(Kg + (size_t)(kbase + row) * HD + c4);
            Kst[c4 + 0][row ^ KSW(c4 + 0)] = kv.x;
            Kst[c4 + 1][row ^ KSW(c4 + 1)] = kv.y;
            Kst[c4 + 2][row ^ KSW(c4 + 2)] = kv.z;
            Kst[c4 + 3][row ^ KSW(c4 + 3)] = kv.w;
            *(float4*)&Vs[row][c4] = *(const float4*)(Vg + (size_t)(kbase + row) * HD + c4);
        }
        __syncthreads();

        // Scores: s[i][jj] = Q[ty*8+i][:] . K[jj*32+lane][:]
        float s[8][2];
        #pragma unroll
        for (int i = 0; i < 8; ++i) { s[i][0] = 0.0f; s[i][1] = 0.0f; }
        #pragma unroll 4
        for (int d = 0; d < 64; ++d) {
            int swl = lane ^ KSW(d);
            float k0v = Kst[d][swl];
            float k1v = Kst[d][swl + 32];
            #pragma unroll
            for (int i = 0; i < 8; ++i) {
                float qv = Qs[ty * 8 + i][d];
                s[i][0] = fmaf(qv, k0v, s[i][0]);
                s[i][1] = fmaf(qv, k1v, s[i][1]);
            }
        }

        // Mask, online softmax update
        float pr[8][2];
        #pragma unroll
        for (int i = 0; i < 8; ++i) {
            int q = t0 + ty * 8 + i;
            #pragma unroll
            for (int jj = 0; jj < 2; ++jj) {
                int k = kbase + lane + jj * 32;
                bool ok = (k <= q) && ((k < PREFIX) || ((q - k) < WINDOW));
                if (!ok) s[i][jj] = -1e30f;
            }
            float mx = fmaxf(s[i][0], s[i][1]);
            #pragma unroll
            for (int off = 16; off > 0; off >>= 1)
                mx = fmaxf(mx, __shfl_xor_sync(0xffffffffu, mx, off));
            float mnew  = fmaxf(m_i[i], mx);
            float scale = __expf(m_i[i] - mnew);
            float p0 = __expf(s[i][0] - mnew);
            float p1 = __expf(s[i][1] - mnew);
            float rs = p0 + p1;
            #pragma unroll
            for (int off = 16; off > 0; off >>= 1)
                rs += __shfl_xor_sync(0xffffffffu, rs, off);
            l_i[i] = l_i[i] * scale + rs;
            m_i[i] = mnew;
            o0[i] *= scale; o1[i] *= scale;
            pr[i][0] = p0; pr[i][1] = p1;
        }

        __syncthreads();   // everyone done reading Kst before P overwrite
        #pragma unroll
        for (int i = 0; i < 8; ++i) {
            Ps[(ty * 8 + i) * 64 + lane]      = pr[i][0];
            Ps[(ty * 8 + i) * 64 + lane + 32] = pr[i][1];
        }
        __syncthreads();

        // O += P * V  (V reads conflict-free; P reads broadcast)
        #pragma unroll 2
        for (int k = 0; k < 64; ++k) {
            float v0 = Vs[k][lane];
            float v1 = Vs[k][lane + 32];
            #pragma unroll
            for (int i = 0; i < 8; ++i) {
                float p = Ps[(ty * 8 + i) * 64 + k];
                o0[i] = fmaf(p, v0, o0[i]);
                o1[i] = fmaf(p, v1, o1[i]);
            }
        }
    }

    // Finalize: g_o[b][s][h*64+d]
    const int b = bh >> 4, h = bh & 15;
    #pragma unroll
    for (int i = 0; i < 8; ++i) {
        int q = t0 + ty * 8 + i;
        float inv = 1.0f / l_i[i];
        float* dst = g_o + ((size_t)b * SEQ + q) * DM + h * HD;
        dst[lane]      = o0[i] * inv;
        dst[lane + 32] = o1[i] * inv;
    }
}

// ---------------------------------------------------------------------------
extern "C" void kernel_launch(void* const* d_in, const int* in_sizes, int n_in,
                              void* d_out, int out_size)
{
    const float* x     = (const float*)d_in[0];
    const float* w_qkv = (const float*)d_in[1];
    const float* w_out = (const float*)d_in[2];
    float* out = (float*)d_out;

    // 1) QKV projection (TF32 tensor cores) with scatter into [bh][s][d]
    gemm_tc<true><<<dim3(3072 / 128, 8192 / 128), 256>>>(x, w_qkv, nullptr);
    // 2) windowed + prefix attention -> g_o [b][s][h*64+d]
    attn_kernel<<<dim3(SEQ / 64, BATCH * NH), 256>>>();
    // 3) output projection (TF32 tensor cores) -> d_out
    gemm_tc<false><<<dim3(1024 / 128, 8192 / 128), 256>>>(nullptr, w_out, out);
}

// round 5
// speedup vs baseline: 3.0180x; 1.5055x over previous
#include <cuda_runtime.h>
#include <cstdint>

#define WINDOW   512
#define PREFIX   16
#define SEQ      4096
#define NH       16
#define BATCH    2
#define DM       1024
#define HD       64

// Scratch (device globals; allocation APIs are forbidden).
__device__ float g_q[(size_t)BATCH * NH * SEQ * HD];   // [b*16+h][s][d] (tf32-rounded, pre-scaled 1/8)
__device__ float g_k[(size_t)BATCH * NH * SEQ * HD];   // tf32-rounded
__device__ float g_v[(size_t)BATCH * NH * SEQ * HD];   // tf32-rounded
__device__ float g_o[(size_t)BATCH * SEQ * DM];        // [b][s][h*64+d]

// ---------------------------------------------------------------------------
__device__ __forceinline__ void cp_async16(unsigned smem_dst, const void* gsrc) {
    asm volatile("cp.async.cg.shared.global [%0], [%1], 16;\n" :: "r"(smem_dst), "l"(gsrc));
}
__device__ __forceinline__ void cp_commit() { asm volatile("cp.async.commit_group;\n"); }
__device__ __forceinline__ void cp_wait0()  { asm volatile("cp.async.wait_group 0;\n"); }

__device__ __forceinline__ unsigned f2tf32(float f) {
    unsigned r;
    asm("cvt.rna.tf32.f32 %0, %1;" : "=r"(r) : "f"(f));
    return r;
}

__device__ __forceinline__ void mma_tf32(float* c, const unsigned* a, const unsigned* b) {
    asm volatile(
        "mma.sync.aligned.m16n8k8.row.col.f32.tf32.tf32.f32 "
        "{%0,%1,%2,%3}, {%4,%5,%6,%7}, {%8,%9}, {%0,%1,%2,%3};\n"
        : "+f"(c[0]), "+f"(c[1]), "+f"(c[2]), "+f"(c[3])
        : "r"(a[0]), "r"(a[1]), "r"(a[2]), "r"(a[3]), "r"(b[0]), "r"(b[1]));
}

// ---------------------------------------------------------------------------
// TF32 tensor-core GEMM (NT): C[m,n] = sum_k A[m,k]*B[n,k].  M=8192, K=1024.
// QKV=true : A = x, scatter tf32-rounded into g_q (x0.125)/g_k/g_v; N=3072.
// QKV=false: A = g_o, plain store to Cout; N=1024.
// ---------------------------------------------------------------------------
#define KP 20   // padded k-stride

template<bool QKV>
__global__ __launch_bounds__(256)
void gemm_tc(const float* __restrict__ Ain,
             const float* __restrict__ Bw,
             float* __restrict__ Cout)
{
    __shared__ float As[2][128 * KP];
    __shared__ float Bs[2][128 * KP];

    const float* A = QKV ? Ain : g_o;

    const int tid  = threadIdx.x;
    const int lane = tid & 31;
    const int wid  = tid >> 5;
    const int wm   = wid >> 2;
    const int wn   = wid & 3;
    const int m0   = blockIdx.y << 7;
    const int n0   = blockIdx.x << 7;
    const int g    = lane >> 2;
    const int t    = lane & 3;

    float acc[4][4][4];
    #pragma unroll
    for (int i = 0; i < 4; ++i)
        #pragma unroll
        for (int j = 0; j < 4; ++j)
            #pragma unroll
            for (int r = 0; r < 4; ++r) acc[i][j][r] = 0.0f;

    const int lrow = tid >> 2;
    const int lcol = (tid & 3) << 2;
    const float* Ag = A  + (size_t)(m0 + lrow) * 1024 + lcol;
    const float* Bg = Bw + (size_t)(n0 + lrow) * 1024 + lcol;

    const unsigned sA0 = (unsigned)__cvta_generic_to_shared(&As[0][lrow * KP + lcol]);
    const unsigned sB0 = (unsigned)__cvta_generic_to_shared(&Bs[0][lrow * KP + lcol]);
    const unsigned bufstride = 128 * KP * 4;
    const unsigned rowstride = 64 * KP * 4;

    cp_async16(sA0,             Ag);
    cp_async16(sA0 + rowstride, Ag + 64 * 1024);
    cp_async16(sB0,             Bg);
    cp_async16(sB0 + rowstride, Bg + 64 * 1024);
    cp_commit();
    cp_wait0();
    __syncthreads();

    int buf = 0;
    for (int kt = 0; kt < 64; ++kt) {
        if (kt + 1 < 64) {
            int k0 = (kt + 1) << 4;
            unsigned sA = sA0 + (unsigned)(buf ^ 1) * bufstride;
            unsigned sB = sB0 + (unsigned)(buf ^ 1) * bufstride;
            cp_async16(sA,             Ag + k0);
            cp_async16(sA + rowstride, Ag + 64 * 1024 + k0);
            cp_async16(sB,             Bg + k0);
            cp_async16(sB + rowstride, Bg + 64 * 1024 + k0);
            cp_commit();
        }

        const float* as = &As[buf][0];
        const float* bs = &Bs[buf][0];
        #pragma unroll
        for (int kk = 0; kk < 16; kk += 8) {
            unsigned af[4][4], bf[4][2];
            #pragma unroll
            for (int im = 0; im < 4; ++im) {
                const float* p = as + (wm * 64 + im * 16 + g) * KP + kk + t;
                af[im][0] = f2tf32(p[0]);
                af[im][1] = f2tf32(p[8 * KP]);
                af[im][2] = f2tf32(p[4]);
                af[im][3] = f2tf32(p[8 * KP + 4]);
            }
            #pragma unroll
            for (int jn = 0; jn < 4; ++jn) {
                const float* p = bs + (wn * 32 + jn * 8 + g) * KP + kk + t;
                bf[jn][0] = f2tf32(p[0]);
                bf[jn][1] = f2tf32(p[4]);
            }
            #pragma unroll
            for (int im = 0; im < 4; ++im)
                #pragma unroll
                for (int jn = 0; jn < 4; ++jn)
                    mma_tf32(acc[im][jn], af[im], bf[jn]);
        }

        cp_wait0();
        __syncthreads();
        buf ^= 1;
    }

    #pragma unroll
    for (int im = 0; im < 4; ++im) {
        #pragma unroll
        for (int jn = 0; jn < 4; ++jn) {
            int row = m0 + wm * 64 + im * 16 + g;
            int col = n0 + wn * 32 + jn * 8 + (t << 1);
            float2 v0 = make_float2(acc[im][jn][0], acc[im][jn][1]);
            float2 v1 = make_float2(acc[im][jn][2], acc[im][jn][3]);
            if (QKV) {
                int part = col >> 10;            // 0:q 1:k 2:v
                float sc = (part == 0) ? 0.125f : 1.0f;
                v0.x = __uint_as_float(f2tf32(v0.x * sc));
                v0.y = __uint_as_float(f2tf32(v0.y * sc));
                v1.x = __uint_as_float(f2tf32(v1.x * sc));
                v1.y = __uint_as_float(f2tf32(v1.y * sc));
                int nn   = col & 1023;
                int h    = nn >> 6;
                int d    = nn & 63;
                float* dst = (part == 0) ? g_q : ((part == 1) ? g_k : g_v);
                int bb = row >> 12, s = row & 4095;
                size_t base = (((size_t)(bb * NH + h)) * SEQ) * HD + d;
                *(float2*)(dst + base + (size_t)s * HD)       = v0;
                *(float2*)(dst + base + (size_t)(s + 8) * HD) = v1;
            } else {
                *(float2*)(Cout + (size_t)row * DM + col)       = v0;
                *(float2*)(Cout + (size_t)(row + 8) * DM + col) = v1;
            }
        }
    }
}

// ---------------------------------------------------------------------------
// Tensor-core flash attention. Block = 128 queries of one (b,h); 8 warps,
// warp w owns query rows [t0+16w, t0+16w+16). Key tiles of 64.
// allowed(q,k) = (k <= q) && (k < 16 || q-k < 512)
// Smem stride 68 words -> all fragment access patterns bank-conflict-free.
// ---------------------------------------------------------------------------
#define ST 68
#define SM_K 0
#define SM_V (64 * ST)
#define SM_Q (2 * 64 * ST)
#define SM_P (SM_Q + 128 * ST)
#define SM_TOT ((SM_P + 128 * ST) * 4)   // bytes = 104448

__global__ __launch_bounds__(256, 2)
void attn_tc()
{
    extern __shared__ float sm[];
    float* Ks = sm + SM_K;
    float* Vs = sm + SM_V;
    float* Qs = sm + SM_Q;
    float* Ps = sm + SM_P;

    const int tid  = threadIdx.x;
    const int lane = tid & 31;
    const int w    = tid >> 5;
    const int g    = lane >> 2;
    const int t    = lane & 3;
    const int bh   = blockIdx.y;
    const int t0   = blockIdx.x << 7;

    const float* Qg = g_q + (size_t)bh * SEQ * HD + (size_t)t0 * HD;
    const float* Kg = g_k + (size_t)bh * SEQ * HD;
    const float* Vg = g_v + (size_t)bh * SEQ * HD;

    // Stage Q (already tf32-valued & pre-scaled) into Qs: 2048 float4
    #pragma unroll
    for (int it = 0; it < 8; ++it) {
        int idx = tid + (it << 8);
        int row = idx >> 4;
        int c4  = (idx & 15) << 2;
        *(float4*)&Qs[row * ST + c4] = *(const float4*)(Qg + row * 64 + c4);
    }

    const int r0 = t0 + w * 16 + g;    // absolute query rows for this thread
    const int r1 = r0 + 8;

    float oa[8][4];
    #pragma unroll
    for (int j = 0; j < 8; ++j)
        #pragma unroll
        for (int r = 0; r < 4; ++r) oa[j][r] = 0.0f;
    float m0 = -1e30f, m1 = -1e30f, l0 = 0.0f, l1 = 0.0f;

    int lo = t0 - (WINDOW - 1); if (lo < 0) lo = 0;
    const int lo_tile = lo >> 6;
    const int hi_tile = (t0 + 127) >> 6;
    const int extra   = (lo_tile > 0) ? 1 : 0;
    const int ntiles  = hi_tile - lo_tile + 1 + extra;

    const int prow = (w * 16 + g) * ST;     // warp P/Q row base (row g)
    const int qrow = prow;

    for (int it = 0; it < ntiles; ++it) {
        int kt = extra ? ((it == 0) ? 0 : (lo_tile + it - 1)) : (lo_tile + it);
        int kbase = kt << 6;

        __syncthreads();
        // K and V tiles: 64x64 floats = 1024 float4 each -> 4 iterations
        #pragma unroll
        for (int it2 = 0; it2 < 4; ++it2) {
            int idx = tid + (it2 << 8);
            int row = idx >> 4;
            int c4  = (idx & 15) << 2;
            *(float4*)&Ks[row * ST + c4] = *(const float4*)(Kg + (size_t)(kbase + row) * 64 + c4);
            *(float4*)&Vs[row * ST + c4] = *(const float4*)(Vg + (size_t)(kbase + row) * 64 + c4);
        }
        __syncthreads();

        // S = Q K^T : warp computes 16 x 64
        float sc[8][4];
        #pragma unroll
        for (int j = 0; j < 8; ++j)
            #pragma unroll
            for (int r = 0; r < 4; ++r) sc[j][r] = 0.0f;

        #pragma unroll
        for (int kk = 0; kk < 8; ++kk) {
            unsigned qa[4];
            const float* qp = &Qs[qrow + kk * 8 + t];
            qa[0] = __float_as_uint(qp[0]);
            qa[1] = __float_as_uint(qp[8 * ST]);
            qa[2] = __float_as_uint(qp[4]);
            qa[3] = __float_as_uint(qp[8 * ST + 4]);
            #pragma unroll
            for (int j = 0; j < 8; ++j) {
                unsigned bb[2];
                const float* kp = &Ks[(j * 8 + g) * ST + kk * 8 + t];
                bb[0] = __float_as_uint(kp[0]);
                bb[1] = __float_as_uint(kp[4]);
                mma_tf32(sc[j], qa, bb);
            }
        }

        // Mask + row max
        float rmax0 = -1e30f, rmax1 = -1e30f;
        #pragma unroll
        for (int j = 0; j < 8; ++j) {
            int kc0 = kbase + j * 8 + (t << 1);
            int kc1 = kc0 + 1;
            bool a00 = (kc0 <= r0) && ((kc0 < PREFIX) || ((r0 - kc0) < WINDOW));
            bool a01 = (kc1 <= r0) && ((kc1 < PREFIX) || ((r0 - kc1) < WINDOW));
            bool a10 = (kc0 <= r1) && ((kc0 < PREFIX) || ((r1 - kc0) < WINDOW));
            bool a11 = (kc1 <= r1) && ((kc1 < PREFIX) || ((r1 - kc1) < WINDOW));
            if (!a00) sc[j][0] = -1e30f;
            if (!a01) sc[j][1] = -1e30f;
            if (!a10) sc[j][2] = -1e30f;
            if (!a11) sc[j][3] = -1e30f;
            rmax0 = fmaxf(rmax0, fmaxf(sc[j][0], sc[j][1]));
            rmax1 = fmaxf(rmax1, fmaxf(sc[j][2], sc[j][3]));
        }
        rmax0 = fmaxf(rmax0, __shfl_xor_sync(0xffffffffu, rmax0, 1));
        rmax0 = fmaxf(rmax0, __shfl_xor_sync(0xffffffffu, rmax0, 2));
        rmax1 = fmaxf(rmax1, __shfl_xor_sync(0xffffffffu, rmax1, 1));
        rmax1 = fmaxf(rmax1, __shfl_xor_sync(0xffffffffu, rmax1, 2));

        // clamp: fully-masked tile -> p underflows to 0 instead of exp(0)=1
        float mn0 = fmaxf(fmaxf(m0, rmax0), -1e28f);
        float mn1 = fmaxf(fmaxf(m1, rmax1), -1e28f);
        float esc0 = __expf(m0 - mn0);
        float esc1 = __expf(m1 - mn1);

        float rs0 = 0.0f, rs1 = 0.0f;
        #pragma unroll
        for (int j = 0; j < 8; ++j) {
            float p0 = __expf(sc[j][0] - mn0);
            float p1 = __expf(sc[j][1] - mn0);
            float p2 = __expf(sc[j][2] - mn1);
            float p3 = __expf(sc[j][3] - mn1);
            rs0 += p0 + p1;
            rs1 += p2 + p3;
            int col = j * 8 + (t << 1);
            *(float2*)&Ps[prow + col] =
                make_float2(__uint_as_float(f2tf32(p0)), __uint_as_float(f2tf32(p1)));
            *(float2*)&Ps[prow + 8 * ST + col] =
                make_float2(__uint_as_float(f2tf32(p2)), __uint_as_float(f2tf32(p3)));
        }
        rs0 += __shfl_xor_sync(0xffffffffu, rs0, 1);
        rs0 += __shfl_xor_sync(0xffffffffu, rs0, 2);
        rs1 += __shfl_xor_sync(0xffffffffu, rs1, 1);
        rs1 += __shfl_xor_sync(0xffffffffu, rs1, 2);

        l0 = l0 * esc0 + rs0;
        l1 = l1 * esc1 + rs1;
        m0 = mn0;
        m1 = mn1;
        #pragma unroll
        for (int j = 0; j < 8; ++j) {
            oa[j][0] *= esc0; oa[j][1] *= esc0;
            oa[j][2] *= esc1; oa[j][3] *= esc1;
        }
        __syncwarp();

        // O += P V : warp computes 16 x 64  (P is warp-local in smem)
        #pragma unroll
        for (int kk = 0; kk < 8; ++kk) {
            unsigned pa[4];
            const float* pp = &Ps[prow + kk * 8 + t];
            pa[0] = __float_as_uint(pp[0]);
            pa[1] = __float_as_uint(pp[8 * ST]);
            pa[2] = __float_as_uint(pp[4]);
            pa[3] = __float_as_uint(pp[8 * ST + 4]);
            #pragma unroll
            for (int j = 0; j < 8; ++j) {
                unsigned bb[2];
                const float* vp = &Vs[(kk * 8 + t) * ST + j * 8 + g];
                bb[0] = __float_as_uint(vp[0]);
                bb[1] = __float_as_uint(vp[4 * ST]);
                mma_tf32(oa[j], pa, bb);
            }
        }
    }

    // Finalize: g_o[b][s][h*64+d]
    const int b = bh >> 4, h = bh & 15;
    const float inv0 = 1.0f / l0;
    const float inv1 = 1.0f / l1;
    float* d0 = g_o + ((size_t)b * SEQ + r0) * DM + h * HD;
    float* d1 = g_o + ((size_t)b * SEQ + r1) * DM + h * HD;
    #pragma unroll
    for (int j = 0; j < 8; ++j) {
        int col = j * 8 + (t << 1);
        *(float2*)&d0[col] = make_float2(oa[j][0] * inv0, oa[j][1] * inv0);
        *(float2*)&d1[col] = make_float2(oa[j][2] * inv1, oa[j][3] * inv1);
    }
}

// ---------------------------------------------------------------------------
extern "C" void kernel_launch(void* const* d_in, const int* in_sizes, int n_in,
                              void* d_out, int out_size)
{
    const float* x     = (const float*)d_in[0];
    const float* w_qkv = (const float*)d_in[1];
    const float* w_out = (const float*)d_in[2];
    float* out = (float*)d_out;

    cudaFuncSetAttribute(attn_tc, cudaFuncAttributeMaxDynamicSharedMemorySize, SM_TOT);

    // 1) QKV projection (TF32 tensor cores), tf32-rounded scatter into [bh][s][d]
    gemm_tc<true><<<dim3(3072 / 128, 8192 / 128), 256>>>(x, w_qkv, nullptr);
    // 2) tensor-core flash attention -> g_o [b][s][h*64+d]
    attn_tc<<<dim3(SEQ / 128, BATCH * NH), 256, SM_TOT>>>();
    // 3) output projection (TF32 tensor cores) -> d_out
    gemm_tc<false><<<dim3(1024 / 128, 8192 / 128), 256>>>(nullptr, w_out, out);
}